// round 2
// baseline (speedup 1.0000x reference)
#include <cuda_runtime.h>

// Problem constants
#define BB      64      // batch
#define HL      8       // hat_L
#define NPTS    16      // N
#define DDIM    32      // d
#define FLAYER  512     // N*d
#define FTOT    4096    // hat_L*N*d
#define NCHUNK  16      // feature chunks per layer for Gram partials
#define CF      32      // features per chunk (FLAYER / NCHUNK)

// -------- device scratch (no allocations allowed) --------
__device__ float g_Zc[2][BB * FTOT];                 // centered Z (s, t)   : 2 MB
__device__ float g_P[3 * HL * NCHUNK * 4096];        // partial Grams       : 6 MB
__device__ float g_C[2][HL * NPTS * DDIM * DDIM];    // node covariances /63
__device__ float g_Wnum[3 * HL];                     // ||G_t||_F^2 per (type, t)
__device__ float g_exo_part[3 * 8];                  // ||G_full||^2 partials per (type, seg)
__device__ float g_sca[HL];
__device__ float g_sfa[HL * NPTS];

// ============================================================
// K1: center Z (both tensors) + per-layer L_sca from E variances
// grid: 40 blocks x 256 threads.
// ============================================================
__global__ void k1_center_sca(const float* __restrict__ Zs,
                              const float* __restrict__ Es,
                              const float* __restrict__ Zt,
                              const float* __restrict__ Et) {
    int blk = blockIdx.x, tid = threadIdx.x;
    if (blk < 32) {
        int g = blk * 256 + tid;          // 0..8191
        int tensor = g >> 12;             // 0 = s, 1 = t
        int f = g & 4095;
        const float* Z = tensor ? Zt : Zs;
        float v[BB];
        float s = 0.0f;
        #pragma unroll
        for (int b = 0; b < BB; b++) {
            v[b] = Z[b * FTOT + f];
            s += v[b];
        }
        float m = s * (1.0f / (float)BB);
        float* out = g_Zc[tensor];
        #pragma unroll
        for (int b = 0; b < BB; b++)
            out[b * FTOT + f] = v[b] - m;
    } else {
        // L_sca: var over B (ddof=1) of E_s/E_t per (t, m, n)
        int t = blk - 32;
        int base = t * (NPTS * NPTS) + tid;   // tid = m*16+n, 0..255
        float ss = 0.f, sqs = 0.f, st = 0.f, sqt = 0.f;
        #pragma unroll 8
        for (int b = 0; b < BB; b++) {
            float a = Es[b * (HL * NPTS * NPTS) + base];
            ss += a; sqs += a * a;
            float c = Et[b * (HL * NPTS * NPTS) + base];
            st += c; sqt += c * c;
        }
        float var_s = (sqs - ss * ss * (1.0f / (float)BB)) * (1.0f / (float)(BB - 1));
        float var_t = (sqt - st * st * (1.0f / (float)BB)) * (1.0f / (float)(BB - 1));
        float d = var_s - var_t;
        float val = d * d * 0.25f;
        __shared__ float red[256];
        red[tid] = val;
        __syncthreads();
        for (int s2 = 128; s2 > 0; s2 >>= 1) {
            if (tid < s2) red[tid] += red[tid + s2];
            __syncthreads();
        }
        if (tid == 0) g_sca[t] = red[0] * (1.0f / 256.0f);
    }
}

// ============================================================
// K2: per-(layer, chunk) partial Grams  +  per-(t,n) node covariances
// grid: 256 blocks x 256 threads.
// ============================================================
__global__ void k2_grams_covs() {
    int blk = blockIdx.x, tid = threadIdx.x;
    if (blk < 128) {
        int t = blk >> 4, c = blk & 15;
        __shared__ __align__(16) float St_s[CF][68];
        __shared__ __align__(16) float St_t[CF][68];
        int fbase = t * FLAYER + c * CF;
        for (int k = tid; k < BB * CF; k += 256) {
            int b = k >> 5, f = k & 31;            // coalesced gmem read
            St_s[f][b] = g_Zc[0][b * FTOT + fbase + f];
            St_t[f][b] = g_Zc[1][b * FTOT + fbase + f];
        }
        __syncthreads();
        int ri = tid & 15, ci = tid >> 4;          // 4x4 output tile per thread
        float a_ss[4][4] = {}, a_tt[4][4] = {}, a_st[4][4] = {};
        #pragma unroll 4
        for (int f = 0; f < CF; f++) {
            float4 v;
            float As[4], Bs[4], At[4], Bt[4];
            v = *(const float4*)&St_s[f][4 * ri]; As[0]=v.x; As[1]=v.y; As[2]=v.z; As[3]=v.w;
            v = *(const float4*)&St_s[f][4 * ci]; Bs[0]=v.x; Bs[1]=v.y; Bs[2]=v.z; Bs[3]=v.w;
            v = *(const float4*)&St_t[f][4 * ri]; At[0]=v.x; At[1]=v.y; At[2]=v.z; At[3]=v.w;
            v = *(const float4*)&St_t[f][4 * ci]; Bt[0]=v.x; Bt[1]=v.y; Bt[2]=v.z; Bt[3]=v.w;
            #pragma unroll
            for (int i = 0; i < 4; i++)
                #pragma unroll
                for (int j = 0; j < 4; j++) {
                    a_ss[i][j] += As[i] * Bs[j];
                    a_tt[i][j] += At[i] * Bt[j];
                    a_st[i][j] += As[i] * Bt[j];
                }
        }
        float* p0 = &g_P[((0 * HL + t) * NCHUNK + c) * 4096];
        float* p1 = &g_P[((1 * HL + t) * NCHUNK + c) * 4096];
        float* p2 = &g_P[((2 * HL + t) * NCHUNK + c) * 4096];
        #pragma unroll
        for (int i = 0; i < 4; i++)
            #pragma unroll
            for (int j = 0; j < 4; j++) {
                int o = (4 * ri + i) * 64 + 4 * ci + j;
                p0[o] = a_ss[i][j];
                p1[o] = a_tt[i][j];
                p2[o] = a_st[i][j];
            }
    } else {
        // node covariances: C[t,n] = Xc^T Xc / 63, Xc = g_Zc[:, t, n, :]  [64 x 32]
        int id = blk - 128;
        int t = id >> 4, n = id & 15;
        __shared__ __align__(16) float Xs[BB * DDIM];
        __shared__ __align__(16) float Xt[BB * DDIM];
        int base = t * FLAYER + n * DDIM;
        for (int k = tid; k < BB * DDIM; k += 256) {
            int b = k >> 5, dd = k & 31;
            Xs[k] = g_Zc[0][b * FTOT + base + dd];
            Xt[k] = g_Zc[1][b * FTOT + base + dd];
        }
        __syncthreads();
        int ai = tid & 15, bi = tid >> 4;          // 2x2 output tile
        float cs[2][2] = {}, ct[2][2] = {};
        #pragma unroll 8
        for (int b = 0; b < BB; b++) {
            float2 va = *(const float2*)&Xs[b * DDIM + 2 * ai];
            float2 vb = *(const float2*)&Xs[b * DDIM + 2 * bi];
            float2 wa = *(const float2*)&Xt[b * DDIM + 2 * ai];
            float2 wb = *(const float2*)&Xt[b * DDIM + 2 * bi];
            cs[0][0] += va.x * vb.x; cs[0][1] += va.x * vb.y;
            cs[1][0] += va.y * vb.x; cs[1][1] += va.y * vb.y;
            ct[0][0] += wa.x * wb.x; ct[0][1] += wa.x * wb.y;
            ct[1][0] += wa.y * wb.x; ct[1][1] += wa.y * wb.y;
        }
        const float inv63 = 1.0f / 63.0f;
        int cbase = (t * NPTS + n) * (DDIM * DDIM);
        #pragma unroll
        for (int i = 0; i < 2; i++)
            #pragma unroll
            for (int j = 0; j < 2; j++) {
                int o = cbase + (2 * ai + i) * DDIM + (2 * bi + j);
                g_C[0][o] = cs[i][j] * inv63;
                g_C[1][o] = ct[i][j] * inv63;
            }
    }
}

// ============================================================
// K3: per-(t,n) contrastive log term + per-layer ||G_t||^2 + full-Gram ||.||^2 partials
// grid: 176 blocks x 512 threads.
//   blocks 0..127  : sfa term for (t,n); warp w handles column j=w
//   blocks 128..151: reduce 16 chunk partials -> ||G_t||^2 for gram g = blk-128
//   blocks 152..175: full-Gram partial: type = id/8, seg = id%8 (512 elements each),
//                    sum all 128 (t,c) partials per element, square, block-reduce
// ============================================================
__global__ void k3_sfa_gramred() {
    int blk = blockIdx.x, tid = threadIdx.x;
    if (blk < 128) {
        int t = blk >> 4, n = blk & 15;
        int w = tid >> 5, lane = tid & 31;        // w = j in 0..15
        const float* Cs = &g_C[0][(t * NPTS + n) * (DDIM * DDIM)];
        const float* Ct = &g_C[1][(t * NPTS + w) * (DDIM * DDIM)];
        float dot = 0.f, sqt = 0.f, sqs = 0.f;
        #pragma unroll 8
        for (int k = lane; k < DDIM * DDIM; k += 32) {
            float a = Cs[k], b = Ct[k];
            dot += a * b;
            sqt += b * b;
            sqs += a * a;
        }
        #pragma unroll
        for (int o = 16; o > 0; o >>= 1) {
            dot += __shfl_xor_sync(0xFFFFFFFFu, dot, o);
            sqt += __shfl_xor_sync(0xFFFFFFFFu, sqt, o);
            sqs += __shfl_xor_sync(0xFFFFFFFFu, sqs, o);
        }
        __shared__ float sm_st[16], sm_tt[16], sm_ss;
        if (lane == 0) {
            sm_st[w] = dot;
            sm_tt[w] = sqt;
            if (w == 0) sm_ss = sqs;
        }
        __syncthreads();
        if (tid == 0) {
            float ss = sm_ss;
            float Dsum = 0.f, pos = 0.f;
            #pragma unroll
            for (int j = 0; j < 16; j++) {
                float Dj = (ss + sm_tt[j] - 2.0f * sm_st[j]) * (1.0f / 4096.0f);
                Dsum += Dj;
                if (j == n) pos = Dj;
            }
            float neg = Dsum - pos;
            float ep = expf(pos);
            g_sfa[t * NPTS + n] = logf(ep + neg + 1e-8f) - pos;
        }
    } else if (blk < 152) {
        int g = blk - 128;                        // 0..23 == type*8 + t
        const float* Pbase = &g_P[g * NCHUNK * 4096];
        float sq = 0.f;
        for (int i = tid; i < 4096; i += 512) {
            float v = 0.f;
            #pragma unroll
            for (int c = 0; c < NCHUNK; c++) v += Pbase[c * 4096 + i];
            sq += v * v;
        }
        __shared__ float red[512];
        red[tid] = sq;
        __syncthreads();
        for (int s2 = 256; s2 > 0; s2 >>= 1) {
            if (tid < s2) red[tid] += red[tid + s2];
            __syncthreads();
        }
        if (tid == 0) g_Wnum[g] = red[0];
    } else {
        // full-Gram norm partials: element i of G_full[type] = sum of 128 partials
        int id = blk - 152;                       // 0..23
        int type = id >> 3, seg = id & 7;
        int i = seg * 512 + tid;                  // one element per thread
        const float* Pbase = &g_P[type * HL * NCHUNK * 4096];
        float v = 0.f;
        #pragma unroll 8
        for (int tc = 0; tc < HL * NCHUNK; tc++)
            v += Pbase[tc * 4096 + i];
        float sq = v * v;
        __shared__ float red[512];
        red[tid] = sq;
        __syncthreads();
        for (int s2 = 256; s2 > 0; s2 >>= 1) {
            if (tid < s2) red[tid] += red[tid + s2];
            __syncthreads();
        }
        if (tid == 0) g_exo_part[type * 8 + seg] = red[0];
    }
}

// ============================================================
// K4: tiny scalar combine. 1 block x 32 threads.
// ============================================================
__global__ void k4_final(float* __restrict__ out) {
    int lane = threadIdx.x;
    const float exo_scale = (float)(1.0 / (3969.0 * 4.0 * 16777216.0));
    const float w_scale   = (float)(1.0 / (3969.0 * 4.0 * 262144.0));
    float val = 0.f;
    if (lane < 8) {
        int t = lane;
        float W = (g_Wnum[t] + g_Wnum[HL + t] - 2.0f * g_Wnum[2 * HL + t]) * w_scale;
        float sfa = 0.f;
        #pragma unroll
        for (int n = 0; n < NPTS; n++) sfa += g_sfa[t * NPTS + n];
        sfa *= (1.0f / (float)NPTS);
        val = W * (0.1f * g_sca[t] + 0.1f * sfa) * (1.0f / (float)HL);
    } else {
        int id = lane - 8;                        // 0..23
        int type = id >> 3, seg = id & 7;
        float coef = (type == 2) ? -2.0f : 1.0f;
        val = g_exo_part[type * 8 + seg] * coef * exo_scale;
    }
    #pragma unroll
    for (int o = 16; o > 0; o >>= 1)
        val += __shfl_xor_sync(0xFFFFFFFFu, val, o);
    if (lane == 0) out[0] = val;
}

// ============================================================
extern "C" void kernel_launch(void* const* d_in, const int* in_sizes, int n_in,
                              void* d_out, int out_size) {
    const float* Zs = (const float*)d_in[0];
    const float* Es = (const float*)d_in[1];
    const float* Zt = (const float*)d_in[2];
    const float* Et = (const float*)d_in[3];
    float* out = (float*)d_out;

    k1_center_sca<<<40, 256>>>(Zs, Es, Zt, Et);
    k2_grams_covs<<<256, 256>>>();
    k3_sfa_gramred<<<176, 512>>>();
    k4_final<<<1, 32>>>(out);
}

// round 3
// speedup vs baseline: 1.0037x; 1.0037x over previous
#include <cuda_runtime.h>

// Problem constants
#define BB      64      // batch
#define HL      8       // hat_L
#define NPTS    16      // N
#define DDIM    32      // d
#define FLAYER  512     // N*d
#define FTOT    4096    // hat_L*N*d
#define NCHUNK  16      // feature chunks per layer == nodes per layer (CF == DDIM)
#define NBLK    136     // 128 gram+cov blocks + 8 sca blocks
#define NTASK2  176     // phase-2 tasks: 128 sfa + 24 Wnum + 24 exo

// -------- device scratch (no allocations allowed) --------
__device__ float g_P[3 * HL * NCHUNK * 4096];        // partial Grams       : 6 MB
__device__ float g_C[2][HL * NPTS * DDIM * DDIM];    // node covariances /63
__device__ float g_Wnum[3 * HL];                     // ||G_t||_F^2 per (type, t)
__device__ float g_exo_part[3 * 8];                  // ||G_full||^2 partials
__device__ float g_sca[HL];
__device__ float g_sfa[HL * NPTS];
__device__ unsigned int g_barcnt[2];                 // monotonic barrier tickets

// Replay-safe grid barrier: monotonic ticket counter, no reset needed.
__device__ __forceinline__ void grid_barrier(int which) {
    __syncthreads();
    if (threadIdx.x == 0) {
        __threadfence();
        unsigned int ticket = atomicAdd(&g_barcnt[which], 1u);
        unsigned int target = (ticket / NBLK + 1u) * NBLK;
        while (true) {
            unsigned int v;
            asm volatile("ld.acquire.gpu.u32 %0, [%1];"
                         : "=r"(v) : "l"(&g_barcnt[which]));
            if ((int)(v - target) >= 0) break;
            __nanosleep(32);
        }
    }
    __syncthreads();
}

__global__ void __launch_bounds__(256) fused_all(
        const float* __restrict__ Zs, const float* __restrict__ Es,
        const float* __restrict__ Zt, const float* __restrict__ Et,
        float* __restrict__ out) {
    int blk = blockIdx.x, tid = threadIdx.x;

    __shared__ __align__(16) float St_s[DDIM][68];   // [f][b] transposed, padded
    __shared__ __align__(16) float St_t[DDIM][68];
    __shared__ __align__(16) float Xs[BB * DDIM];    // [b][f] row-major
    __shared__ __align__(16) float Xt[BB * DDIM];
    __shared__ float red[256];
    __shared__ float sm_st[16], sm_tt[16], sm_ss;

    // ================= PHASE 1 =================
    if (blk < 128) {
        // gram chunk == node: (t, nn) slice of 32 features x 64 batch
        int t = blk >> 4, nn = blk & 15;
        int fbase = t * FLAYER + nn * DDIM;
        for (int k = tid; k < BB * DDIM; k += 256) {
            int b = k >> 5, f = k & 31;
            float vs = Zs[b * FTOT + fbase + f];
            float vt = Zt[b * FTOT + fbase + f];
            St_s[f][b] = vs; Xs[b * DDIM + f] = vs;
            St_t[f][b] = vt; Xt[b * DDIM + f] = vt;
        }
        __syncthreads();
        // local centering: per-feature mean over B
        if (tid < 64) {
            int tensor = tid >> 5, f = tid & 31;
            float (*St)[68] = tensor ? St_t : St_s;
            float* X = tensor ? Xt : Xs;
            float s = 0.f;
            #pragma unroll
            for (int b = 0; b < BB; b++) s += St[f][b];
            float m = s * (1.0f / (float)BB);
            #pragma unroll
            for (int b = 0; b < BB; b++) {
                St[f][b] -= m;
                X[b * DDIM + f] -= m;
            }
        }
        __syncthreads();

        // ---- 64x64 batch-Gram partials (4x4 tile per thread) ----
        {
            int ri = tid & 15, ci = tid >> 4;
            float a_ss[4][4] = {}, a_tt[4][4] = {}, a_st[4][4] = {};
            #pragma unroll 4
            for (int f = 0; f < DDIM; f++) {
                float4 v;
                float As[4], Bs[4], At[4], Bt[4];
                v = *(const float4*)&St_s[f][4 * ri]; As[0]=v.x; As[1]=v.y; As[2]=v.z; As[3]=v.w;
                v = *(const float4*)&St_s[f][4 * ci]; Bs[0]=v.x; Bs[1]=v.y; Bs[2]=v.z; Bs[3]=v.w;
                v = *(const float4*)&St_t[f][4 * ri]; At[0]=v.x; At[1]=v.y; At[2]=v.z; At[3]=v.w;
                v = *(const float4*)&St_t[f][4 * ci]; Bt[0]=v.x; Bt[1]=v.y; Bt[2]=v.z; Bt[3]=v.w;
                #pragma unroll
                for (int i = 0; i < 4; i++)
                    #pragma unroll
                    for (int j = 0; j < 4; j++) {
                        a_ss[i][j] += As[i] * Bs[j];
                        a_tt[i][j] += At[i] * Bt[j];
                        a_st[i][j] += As[i] * Bt[j];
                    }
            }
            float* p0 = &g_P[((0 * HL + t) * NCHUNK + nn) * 4096];
            float* p1 = &g_P[((1 * HL + t) * NCHUNK + nn) * 4096];
            float* p2 = &g_P[((2 * HL + t) * NCHUNK + nn) * 4096];
            #pragma unroll
            for (int i = 0; i < 4; i++)
                #pragma unroll
                for (int j = 0; j < 4; j++) {
                    int o = (4 * ri + i) * 64 + 4 * ci + j;
                    p0[o] = a_ss[i][j];
                    p1[o] = a_tt[i][j];
                    p2[o] = a_st[i][j];
                }
        }

        // ---- 32x32 node covariance (2x2 tile per thread), same slice ----
        {
            int ai = tid & 15, bi = tid >> 4;
            float cs[2][2] = {}, ct[2][2] = {};
            #pragma unroll 8
            for (int b = 0; b < BB; b++) {
                float2 va = *(const float2*)&Xs[b * DDIM + 2 * ai];
                float2 vb = *(const float2*)&Xs[b * DDIM + 2 * bi];
                float2 wa = *(const float2*)&Xt[b * DDIM + 2 * ai];
                float2 wb = *(const float2*)&Xt[b * DDIM + 2 * bi];
                cs[0][0] += va.x * vb.x; cs[0][1] += va.x * vb.y;
                cs[1][0] += va.y * vb.x; cs[1][1] += va.y * vb.y;
                ct[0][0] += wa.x * wb.x; ct[0][1] += wa.x * wb.y;
                ct[1][0] += wa.y * wb.x; ct[1][1] += wa.y * wb.y;
            }
            const float inv63 = 1.0f / 63.0f;
            int cbase = (t * NPTS + nn) * (DDIM * DDIM);
            #pragma unroll
            for (int i = 0; i < 2; i++)
                #pragma unroll
                for (int j = 0; j < 2; j++) {
                    int o = cbase + (2 * ai + i) * DDIM + (2 * bi + j);
                    g_C[0][o] = cs[i][j] * inv63;
                    g_C[1][o] = ct[i][j] * inv63;
                }
        }
    } else {
        // ---- L_sca for layer t (8 blocks) ----
        int t = blk - 128;
        int base = t * (NPTS * NPTS) + tid;   // tid = 0..255
        float ss = 0.f, sqs = 0.f, st = 0.f, sqt = 0.f;
        #pragma unroll 8
        for (int b = 0; b < BB; b++) {
            float a = Es[b * (HL * NPTS * NPTS) + base];
            ss += a; sqs += a * a;
            float c = Et[b * (HL * NPTS * NPTS) + base];
            st += c; sqt += c * c;
        }
        float var_s = (sqs - ss * ss * (1.0f / (float)BB)) * (1.0f / (float)(BB - 1));
        float var_t = (sqt - st * st * (1.0f / (float)BB)) * (1.0f / (float)(BB - 1));
        float d = var_s - var_t;
        red[tid] = d * d * 0.25f;
        __syncthreads();
        for (int s2 = 128; s2 > 0; s2 >>= 1) {
            if (tid < s2) red[tid] += red[tid + s2];
            __syncthreads();
        }
        if (tid == 0) g_sca[t] = red[0] * (1.0f / 256.0f);
    }

    grid_barrier(0);

    // ================= PHASE 2 =================
    for (int task = blk; task < NTASK2; task += NBLK) {
        __syncthreads();
        if (task < 128) {
            // sfa term for (t, n); warp w handles columns j = w and j = w+8
            int t = task >> 4, n = task & 15;
            int w = tid >> 5, lane = tid & 31;
            const float* Cs  = &g_C[0][(t * NPTS + n)       * (DDIM * DDIM)];
            const float* Ct1 = &g_C[1][(t * NPTS + w)       * (DDIM * DDIM)];
            const float* Ct2 = &g_C[1][(t * NPTS + w + 8)   * (DDIM * DDIM)];
            float sqs = 0.f, d1 = 0.f, q1 = 0.f, d2 = 0.f, q2 = 0.f;
            #pragma unroll 8
            for (int k = lane; k < DDIM * DDIM; k += 32) {
                float a = Cs[k], b1 = Ct1[k], b2 = Ct2[k];
                sqs += a * a;
                d1 += a * b1; q1 += b1 * b1;
                d2 += a * b2; q2 += b2 * b2;
            }
            #pragma unroll
            for (int o = 16; o > 0; o >>= 1) {
                sqs += __shfl_xor_sync(0xFFFFFFFFu, sqs, o);
                d1  += __shfl_xor_sync(0xFFFFFFFFu, d1, o);
                q1  += __shfl_xor_sync(0xFFFFFFFFu, q1, o);
                d2  += __shfl_xor_sync(0xFFFFFFFFu, d2, o);
                q2  += __shfl_xor_sync(0xFFFFFFFFu, q2, o);
            }
            if (lane == 0) {
                sm_st[w] = d1;  sm_st[w + 8] = d2;
                sm_tt[w] = q1;  sm_tt[w + 8] = q2;
                if (w == 0) sm_ss = sqs;
            }
            __syncthreads();
            if (tid == 0) {
                float ss = sm_ss;
                float Dsum = 0.f, pos = 0.f;
                #pragma unroll
                for (int j = 0; j < 16; j++) {
                    float Dj = (ss + sm_tt[j] - 2.0f * sm_st[j]) * (1.0f / 4096.0f);
                    Dsum += Dj;
                    if (j == n) pos = Dj;
                }
                float neg = Dsum - pos;
                float ep = expf(pos);
                g_sfa[t * NPTS + n] = logf(ep + neg + 1e-8f) - pos;
            }
        } else if (task < 152) {
            // ||G_t||^2: reduce 16 chunk partials for gram g
            int g = task - 128;                   // type*8 + t
            const float* Pbase = &g_P[g * NCHUNK * 4096];
            float sq = 0.f;
            for (int i = tid; i < 4096; i += 256) {
                float v = 0.f;
                #pragma unroll
                for (int c = 0; c < NCHUNK; c++) v += Pbase[c * 4096 + i];
                sq += v * v;
            }
            red[tid] = sq;
            __syncthreads();
            for (int s2 = 128; s2 > 0; s2 >>= 1) {
                if (tid < s2) red[tid] += red[tid + s2];
                __syncthreads();
            }
            if (tid == 0) g_Wnum[g] = red[0];
        } else {
            // full-Gram norm partial: type, 512-element segment
            int id = task - 152;                  // 0..23
            int type = id >> 3, seg = id & 7;
            const float* Pbase = &g_P[type * HL * NCHUNK * 4096];
            float sq = 0.f;
            #pragma unroll
            for (int e = 0; e < 2; e++) {
                int i = seg * 512 + e * 256 + tid;
                float v = 0.f;
                #pragma unroll 8
                for (int tc = 0; tc < HL * NCHUNK; tc++)
                    v += Pbase[tc * 4096 + i];
                sq += v * v;
            }
            red[tid] = sq;
            __syncthreads();
            for (int s2 = 128; s2 > 0; s2 >>= 1) {
                if (tid < s2) red[tid] += red[tid + s2];
                __syncthreads();
            }
            if (tid == 0) g_exo_part[type * 8 + seg] = red[0];
        }
        __syncthreads();
    }

    grid_barrier(1);

    // ================= PHASE 3 =================
    if (blk == 0 && tid < 32) {
        int lane = tid;
        const float exo_scale = (float)(1.0 / (3969.0 * 4.0 * 16777216.0));
        const float w_scale   = (float)(1.0 / (3969.0 * 4.0 * 262144.0));
        float val = 0.f;
        if (lane < 8) {
            int t = lane;
            float W = (g_Wnum[t] + g_Wnum[HL + t] - 2.0f * g_Wnum[2 * HL + t]) * w_scale;
            float sfa = 0.f;
            #pragma unroll
            for (int n = 0; n < NPTS; n++) sfa += g_sfa[t * NPTS + n];
            sfa *= (1.0f / (float)NPTS);
            val = W * (0.1f * g_sca[t] + 0.1f * sfa) * (1.0f / (float)HL);
        } else {
            int id = lane - 8;                    // 0..23
            int type = id >> 3, seg = id & 7;
            float coef = (type == 2) ? -2.0f : 1.0f;
            val = g_exo_part[type * 8 + seg] * coef * exo_scale;
        }
        #pragma unroll
        for (int o = 16; o > 0; o >>= 1)
            val += __shfl_xor_sync(0xFFFFFFFFu, val, o);
        if (lane == 0) out[0] = val;
    }
}

// ============================================================
extern "C" void kernel_launch(void* const* d_in, const int* in_sizes, int n_in,
                              void* d_out, int out_size) {
    const float* Zs = (const float*)d_in[0];
    const float* Es = (const float*)d_in[1];
    const float* Zt = (const float*)d_in[2];
    const float* Et = (const float*)d_in[3];
    float* out = (float*)d_out;

    fused_all<<<NBLK, 256>>>(Zs, Es, Zt, Et, out);
}

// round 4
// speedup vs baseline: 1.0663x; 1.0624x over previous
#include <cuda_runtime.h>

// Problem constants
#define BB      64      // batch
#define HL      8       // hat_L
#define NPTS    16      // N
#define DDIM    32      // d
#define FLAYER  512     // N*d
#define FTOT    4096    // hat_L*N*d
#define NCH     4       // K-chunks per layer (128 features each)
#define NBLK    176     // grid size
// phase-1 roles: 0..31 gram, 32..159 node-cov, 160..167 sca, 168..175 idle
// phase-2 roles: blk<128 sfa, 128..151 Wnum, 152..175 exo

// -------- device scratch (no allocations allowed) --------
__device__ float g_P[3 * HL * NCH * 4096];           // chunk Gram partials : 1.5 MB
__device__ float g_C[2][HL * NPTS * DDIM * DDIM];    // node covariances /63
__device__ float g_Wnum[3 * HL];
__device__ float g_exo_part[3 * 8];
__device__ float g_sca[HL];
__device__ float g_sfa[HL * NPTS];
__device__ unsigned int g_barcnt;                    // monotonic barrier ticket
__device__ unsigned int g_done;                      // phase-2 completion ticket

// Replay-safe grid barrier: monotonic ticket counter, no reset needed.
__device__ __forceinline__ void grid_barrier() {
    __syncthreads();
    if (threadIdx.x == 0) {
        __threadfence();
        unsigned int ticket = atomicAdd(&g_barcnt, 1u);
        unsigned int target = (ticket / NBLK + 1u) * NBLK;
        while (true) {
            unsigned int v;
            asm volatile("ld.acquire.gpu.u32 %0, [%1];"
                         : "=r"(v) : "l"(&g_barcnt));
            if ((int)(v - target) >= 0) break;
            __nanosleep(32);
        }
    }
    __syncthreads();
}

__global__ void __launch_bounds__(256) fused_all(
        const float* __restrict__ Zs, const float* __restrict__ Es,
        const float* __restrict__ Zt, const float* __restrict__ Et,
        float* __restrict__ out) {
    int blk = blockIdx.x, tid = threadIdx.x;

    __shared__ __align__(16) float St_s[DDIM][68];   // [f][b] transposed, padded
    __shared__ __align__(16) float St_t[DDIM][68];
    __shared__ __align__(16) float Xs[BB * DDIM];    // [b][f] row-major (cov path)
    __shared__ __align__(16) float Xt[BB * DDIM];
    __shared__ float sm_ps[DDIM * 8], sm_pt[DDIM * 8];   // mean partials
    __shared__ float sm_ms[DDIM], sm_mt[DDIM];           // means
    __shared__ float red[256];
    __shared__ float sm_st[16], sm_tt[16], sm_ss;
    __shared__ unsigned int sm_last;

    // ================= PHASE 1 =================
    if (blk < 32) {
        // Gram chunk: t = blk>>2, c = blk&3, K = 128 features (4 sub-tiles of 32)
        int t = blk >> 2, c = blk & 3;
        int fbase = t * FLAYER + c * 128;
        int ri = tid >> 4, ci = tid & 15;     // rows 4ri.., cols 4ci.. (coalesced stores)
        float a_ss[4][4] = {}, a_tt[4][4] = {}, a_st[4][4] = {};
        int f0 = tid & 31, b0 = tid >> 5;     // per-thread fixed feature, base batch

        for (int kc = 0; kc < 4; kc++) {
            __syncthreads();                  // protect prior iteration reads
            float ps = 0.f, pt = 0.f;
            #pragma unroll
            for (int j = 0; j < 8; j++) {
                int b = b0 + 8 * j;
                float vs = Zs[b * FTOT + fbase + kc * 32 + f0];
                float vt = Zt[b * FTOT + fbase + kc * 32 + f0];
                St_s[f0][b] = vs; ps += vs;
                St_t[f0][b] = vt; pt += vt;
            }
            sm_ps[f0 * 8 + b0] = ps;
            sm_pt[f0 * 8 + b0] = pt;
            __syncthreads();
            if (tid < 64) {                   // reduce mean partials
                int f = tid & 31;
                float* P = (tid < 32) ? sm_ps : sm_pt;
                float m = 0.f;
                #pragma unroll
                for (int j = 0; j < 8; j++) m += P[f * 8 + j];
                m *= (1.0f / (float)BB);
                if (tid < 32) sm_ms[f] = m; else sm_mt[f] = m;
            }
            __syncthreads();
            {                                  // subtract means (each thread: its 8 entries)
                float ms = sm_ms[f0], mt = sm_mt[f0];
                #pragma unroll
                for (int j = 0; j < 8; j++) {
                    int b = b0 + 8 * j;
                    St_s[f0][b] -= ms;
                    St_t[f0][b] -= mt;
                }
            }
            __syncthreads();
            // accumulate Gram over this 32-feature sub-tile
            #pragma unroll 4
            for (int f = 0; f < DDIM; f++) {
                float4 v;
                float As[4], Bs[4], At[4], Bt[4];
                v = *(const float4*)&St_s[f][4 * ri]; As[0]=v.x; As[1]=v.y; As[2]=v.z; As[3]=v.w;
                v = *(const float4*)&St_s[f][4 * ci]; Bs[0]=v.x; Bs[1]=v.y; Bs[2]=v.z; Bs[3]=v.w;
                v = *(const float4*)&St_t[f][4 * ri]; At[0]=v.x; At[1]=v.y; At[2]=v.z; At[3]=v.w;
                v = *(const float4*)&St_t[f][4 * ci]; Bt[0]=v.x; Bt[1]=v.y; Bt[2]=v.z; Bt[3]=v.w;
                #pragma unroll
                for (int i = 0; i < 4; i++)
                    #pragma unroll
                    for (int j = 0; j < 4; j++) {
                        a_ss[i][j] += As[i] * Bs[j];
                        a_tt[i][j] += At[i] * Bt[j];
                        a_st[i][j] += As[i] * Bt[j];
                    }
            }
        }
        // coalesced float4 stores
        float* p0 = &g_P[((0 * HL + t) * NCH + c) * 4096];
        float* p1 = &g_P[((1 * HL + t) * NCH + c) * 4096];
        float* p2 = &g_P[((2 * HL + t) * NCH + c) * 4096];
        #pragma unroll
        for (int i = 0; i < 4; i++) {
            int o = (4 * ri + i) * 64 + 4 * ci;
            *(float4*)&p0[o] = make_float4(a_ss[i][0], a_ss[i][1], a_ss[i][2], a_ss[i][3]);
            *(float4*)&p1[o] = make_float4(a_tt[i][0], a_tt[i][1], a_tt[i][2], a_tt[i][3]);
            *(float4*)&p2[o] = make_float4(a_st[i][0], a_st[i][1], a_st[i][2], a_st[i][3]);
        }
    } else if (blk < 160) {
        // node covariance: (t, n) slice 64 batch x 32 features
        int id = blk - 32;
        int t = id >> 4, n = id & 15;
        int base = t * FLAYER + n * DDIM;
        int f0 = tid & 31, b0 = tid >> 5;
        float ps = 0.f, pt = 0.f;
        #pragma unroll
        for (int j = 0; j < 8; j++) {
            int b = b0 + 8 * j;
            float vs = Zs[b * FTOT + base + f0];
            float vt = Zt[b * FTOT + base + f0];
            Xs[b * DDIM + f0] = vs; ps += vs;
            Xt[b * DDIM + f0] = vt; pt += vt;
        }
        sm_ps[f0 * 8 + b0] = ps;
        sm_pt[f0 * 8 + b0] = pt;
        __syncthreads();
        if (tid < 64) {
            int f = tid & 31;
            float* P = (tid < 32) ? sm_ps : sm_pt;
            float m = 0.f;
            #pragma unroll
            for (int j = 0; j < 8; j++) m += P[f * 8 + j];
            m *= (1.0f / (float)BB);
            if (tid < 32) sm_ms[f] = m; else sm_mt[f] = m;
        }
        __syncthreads();
        {
            float ms = sm_ms[f0], mt = sm_mt[f0];
            #pragma unroll
            for (int j = 0; j < 8; j++) {
                int b = b0 + 8 * j;
                Xs[b * DDIM + f0] -= ms;
                Xt[b * DDIM + f0] -= mt;
            }
        }
        __syncthreads();
        int ai = tid & 15, bi = tid >> 4;          // 2x2 output tile
        float cs[2][2] = {}, ct[2][2] = {};
        #pragma unroll 8
        for (int b = 0; b < BB; b++) {
            float2 va = *(const float2*)&Xs[b * DDIM + 2 * ai];
            float2 vb = *(const float2*)&Xs[b * DDIM + 2 * bi];
            float2 wa = *(const float2*)&Xt[b * DDIM + 2 * ai];
            float2 wb = *(const float2*)&Xt[b * DDIM + 2 * bi];
            cs[0][0] += va.x * vb.x; cs[0][1] += va.x * vb.y;
            cs[1][0] += va.y * vb.x; cs[1][1] += va.y * vb.y;
            ct[0][0] += wa.x * wb.x; ct[0][1] += wa.x * wb.y;
            ct[1][0] += wa.y * wb.x; ct[1][1] += wa.y * wb.y;
        }
        const float inv63 = 1.0f / 63.0f;
        int cbase = (t * NPTS + n) * (DDIM * DDIM);
        #pragma unroll
        for (int i = 0; i < 2; i++)
            #pragma unroll
            for (int j = 0; j < 2; j++) {
                int o = cbase + (2 * ai + i) * DDIM + (2 * bi + j);
                g_C[0][o] = cs[i][j] * inv63;
                g_C[1][o] = ct[i][j] * inv63;
            }
    } else if (blk < 168) {
        // L_sca for layer t
        int t = blk - 160;
        int base = t * (NPTS * NPTS) + tid;
        float ss = 0.f, sqs = 0.f, st = 0.f, sqt = 0.f;
        #pragma unroll 8
        for (int b = 0; b < BB; b++) {
            float a = Es[b * (HL * NPTS * NPTS) + base];
            ss += a; sqs += a * a;
            float ccc = Et[b * (HL * NPTS * NPTS) + base];
            st += ccc; sqt += ccc * ccc;
        }
        float var_s = (sqs - ss * ss * (1.0f / (float)BB)) * (1.0f / (float)(BB - 1));
        float var_t = (sqt - st * st * (1.0f / (float)BB)) * (1.0f / (float)(BB - 1));
        float d = var_s - var_t;
        red[tid] = d * d * 0.25f;
        __syncthreads();
        for (int s2 = 128; s2 > 0; s2 >>= 1) {
            if (tid < s2) red[tid] += red[tid + s2];
            __syncthreads();
        }
        if (tid == 0) g_sca[t] = red[0] * (1.0f / 256.0f);
    }
    // blocks 168..175: idle in phase 1

    grid_barrier();

    // ================= PHASE 2 (one task per block) =================
    if (blk < 128) {
        // sfa term for (t, n); warp w handles columns j = w, w+8
        int t = blk >> 4, n = blk & 15;
        int w = tid >> 5, lane = tid & 31;
        const float* Cs  = &g_C[0][(t * NPTS + n)     * (DDIM * DDIM)];
        const float* Ct1 = &g_C[1][(t * NPTS + w)     * (DDIM * DDIM)];
        const float* Ct2 = &g_C[1][(t * NPTS + w + 8) * (DDIM * DDIM)];
        float sqs = 0.f, d1 = 0.f, q1 = 0.f, d2 = 0.f, q2 = 0.f;
        #pragma unroll 8
        for (int k = lane; k < DDIM * DDIM; k += 32) {
            float a = Cs[k], b1 = Ct1[k], b2 = Ct2[k];
            sqs += a * a;
            d1 += a * b1; q1 += b1 * b1;
            d2 += a * b2; q2 += b2 * b2;
        }
        #pragma unroll
        for (int o = 16; o > 0; o >>= 1) {
            sqs += __shfl_xor_sync(0xFFFFFFFFu, sqs, o);
            d1  += __shfl_xor_sync(0xFFFFFFFFu, d1, o);
            q1  += __shfl_xor_sync(0xFFFFFFFFu, q1, o);
            d2  += __shfl_xor_sync(0xFFFFFFFFu, d2, o);
            q2  += __shfl_xor_sync(0xFFFFFFFFu, q2, o);
        }
        if (lane == 0) {
            sm_st[w] = d1;  sm_st[w + 8] = d2;
            sm_tt[w] = q1;  sm_tt[w + 8] = q2;
            if (w == 0) sm_ss = sqs;
        }
        __syncthreads();
        if (tid == 0) {
            float ss = sm_ss;
            float Dsum = 0.f, pos = 0.f;
            #pragma unroll
            for (int j = 0; j < 16; j++) {
                float Dj = (ss + sm_tt[j] - 2.0f * sm_st[j]) * (1.0f / 4096.0f);
                Dsum += Dj;
                if (j == n) pos = Dj;
            }
            float neg = Dsum - pos;
            float ep = expf(pos);
            g_sfa[t * NPTS + n] = logf(ep + neg + 1e-8f) - pos;
        }
    } else if (blk < 152) {
        // ||G_t||^2: reduce 4 chunk partials
        int g = blk - 128;                    // type*8 + t
        const float* Pbase = &g_P[g * NCH * 4096];
        float sq = 0.f;
        for (int i = tid; i < 4096; i += 256) {
            float v = Pbase[i] + Pbase[4096 + i] + Pbase[2 * 4096 + i] + Pbase[3 * 4096 + i];
            sq += v * v;
        }
        red[tid] = sq;
        __syncthreads();
        for (int s2 = 128; s2 > 0; s2 >>= 1) {
            if (tid < s2) red[tid] += red[tid + s2];
            __syncthreads();
        }
        if (tid == 0) g_Wnum[g] = red[0];
    } else {
        // full-Gram norm partial: sum 32 partials per element
        int id = blk - 152;                   // 0..23
        int type = id >> 3, seg = id & 7;
        const float* Pbase = &g_P[type * HL * NCH * 4096];
        float sq = 0.f;
        #pragma unroll
        for (int e = 0; e < 2; e++) {
            int i = seg * 512 + e * 256 + tid;
            float v = 0.f;
            #pragma unroll 8
            for (int tc = 0; tc < HL * NCH; tc++)
                v += Pbase[tc * 4096 + i];
            sq += v * v;
        }
        red[tid] = sq;
        __syncthreads();
        for (int s2 = 128; s2 > 0; s2 >>= 1) {
            if (tid < s2) red[tid] += red[tid + s2];
            __syncthreads();
        }
        if (tid == 0) g_exo_part[type * 8 + seg] = red[0];
    }

    // ================= PHASE 3: last finisher combines =================
    __syncthreads();
    if (tid == 0) {
        __threadfence();
        unsigned int ticket = atomicAdd(&g_done, 1u);
        sm_last = ((ticket % NBLK) == (NBLK - 1)) ? 1u : 0u;
    }
    __syncthreads();
    if (sm_last && tid < 32) {
        __threadfence();                      // acquire-ish: see all fenced writes
        int lane = tid;
        const float exo_scale = (float)(1.0 / (3969.0 * 4.0 * 16777216.0));
        const float w_scale   = (float)(1.0 / (3969.0 * 4.0 * 262144.0));
        float val = 0.f;
        if (lane < 8) {
            int t = lane;
            float W = (g_Wnum[t] + g_Wnum[HL + t] - 2.0f * g_Wnum[2 * HL + t]) * w_scale;
            float sfa = 0.f;
            #pragma unroll
            for (int n = 0; n < NPTS; n++) sfa += g_sfa[t * NPTS + n];
            sfa *= (1.0f / (float)NPTS);
            val = W * (0.1f * g_sca[t] + 0.1f * sfa) * (1.0f / (float)HL);
        } else {
            int id = lane - 8;                // 0..23
            int type = id >> 3, seg = id & 7;
            float coef = (type == 2) ? -2.0f : 1.0f;
            val = g_exo_part[type * 8 + seg] * coef * exo_scale;
        }
        #pragma unroll
        for (int o = 16; o > 0; o >>= 1)
            val += __shfl_xor_sync(0xFFFFFFFFu, val, o);
        if (lane == 0) out[0] = val;
    }
}

// ============================================================
extern "C" void kernel_launch(void* const* d_in, const int* in_sizes, int n_in,
                              void* d_out, int out_size) {
    const float* Zs = (const float*)d_in[0];
    const float* Es = (const float*)d_in[1];
    const float* Zt = (const float*)d_in[2];
    const float* Et = (const float*)d_in[3];
    float* out = (float*)d_out;

    fused_all<<<NBLK, 256>>>(Zs, Es, Zt, Et, out);
}

// round 5
// speedup vs baseline: 1.3137x; 1.2320x over previous
#include <cuda_runtime.h>

// Problem constants
#define BB      64      // batch
#define HL      8       // hat_L
#define NPTS    16      // N
#define DDIM    32      // d
#define FLAYER  512     // N*d
#define FTOT    4096    // hat_L*N*d
#define NCHUNK  16      // feature chunks per layer == nodes (CF == DDIM)
#define NBLK    176     // grid size
// phase-1: 0..127 gram+cov (t,nn), 128..135 sca, 136..175 idle
// phase-2: 0..127 sfa, 128..151 Wnum, 152..175 exo

// -------- device scratch (no allocations allowed) --------
__device__ float g_P[3 * HL * NCHUNK * 4096];        // chunk Gram partials : 6 MB
__device__ float g_C[2][HL * NPTS * DDIM * DDIM];    // node covariances /63
__device__ float g_Wnum[3 * HL];
__device__ float g_exo_part[3 * 8];
__device__ float g_sca[HL];
__device__ float g_sfa[HL * NPTS];
__device__ unsigned int g_barcnt;                    // monotonic barrier ticket
__device__ unsigned int g_done;                      // completion ticket

// Replay-safe grid barrier: monotonic ticket counter, no reset needed.
__device__ __forceinline__ void grid_barrier() {
    __syncthreads();
    if (threadIdx.x == 0) {
        __threadfence();
        unsigned int ticket = atomicAdd(&g_barcnt, 1u);
        unsigned int target = (ticket / NBLK + 1u) * NBLK;
        while (true) {
            unsigned int v;
            asm volatile("ld.acquire.gpu.u32 %0, [%1];"
                         : "=r"(v) : "l"(&g_barcnt));
            if ((int)(v - target) >= 0) break;
            __nanosleep(32);
        }
    }
    __syncthreads();
}

__global__ void __launch_bounds__(256, 2) fused_all(
        const float* __restrict__ Zs, const float* __restrict__ Es,
        const float* __restrict__ Zt, const float* __restrict__ Et,
        float* __restrict__ out) {
    int blk = blockIdx.x, tid = threadIdx.x;

    __shared__ __align__(16) float St_s[DDIM][68];   // [f][b] transposed, padded
    __shared__ __align__(16) float St_t[DDIM][68];
    __shared__ __align__(16) float Xs[BB * DDIM];    // [b][f] row-major (cov path)
    __shared__ __align__(16) float Xt[BB * DDIM];
    __shared__ float sm_ps[DDIM * 8], sm_pt[DDIM * 8];   // mean partials
    __shared__ float sm_ms[DDIM], sm_mt[DDIM];           // means
    __shared__ float red[256];
    __shared__ float sm_st[16], sm_tt[16], sm_ss;
    __shared__ unsigned int sm_last;

    // ================= PHASE 1 =================
    if (blk < 128) {
        // combined gram-chunk + node-cov for (t, nn): slice 64 batch x 32 features
        int t = blk >> 4, nn = blk & 15;
        int fbase = t * FLAYER + nn * DDIM;
        int f0 = tid & 31, b0 = tid >> 5;
        float ps = 0.f, pt = 0.f;
        #pragma unroll
        for (int j = 0; j < 8; j++) {
            int b = b0 + 8 * j;
            float vs = Zs[b * FTOT + fbase + f0];
            float vt = Zt[b * FTOT + fbase + f0];
            St_s[f0][b] = vs; Xs[b * DDIM + f0] = vs; ps += vs;
            St_t[f0][b] = vt; Xt[b * DDIM + f0] = vt; pt += vt;
        }
        sm_ps[f0 * 8 + b0] = ps;
        sm_pt[f0 * 8 + b0] = pt;
        __syncthreads();
        if (tid < 64) {                       // reduce mean partials
            int f = tid & 31;
            float* P = (tid < 32) ? sm_ps : sm_pt;
            float m = 0.f;
            #pragma unroll
            for (int j = 0; j < 8; j++) m += P[f * 8 + j];
            m *= (1.0f / (float)BB);
            if (tid < 32) sm_ms[f] = m; else sm_mt[f] = m;
        }
        __syncthreads();
        {                                      // subtract means in both layouts
            float ms = sm_ms[f0], mt = sm_mt[f0];
            #pragma unroll
            for (int j = 0; j < 8; j++) {
                int b = b0 + 8 * j;
                St_s[f0][b] -= ms; Xs[b * DDIM + f0] -= ms;
                St_t[f0][b] -= mt; Xt[b * DDIM + f0] -= mt;
            }
        }
        __syncthreads();

        // ---- 64x64 batch-Gram partial (4x4 tile, coalesced stores) ----
        {
            int ri = tid >> 4, ci = tid & 15;
            float a_ss[4][4] = {}, a_tt[4][4] = {}, a_st[4][4] = {};
            #pragma unroll 4
            for (int f = 0; f < DDIM; f++) {
                float4 v;
                float As[4], Bs[4], At[4], Bt[4];
                v = *(const float4*)&St_s[f][4 * ri]; As[0]=v.x; As[1]=v.y; As[2]=v.z; As[3]=v.w;
                v = *(const float4*)&St_s[f][4 * ci]; Bs[0]=v.x; Bs[1]=v.y; Bs[2]=v.z; Bs[3]=v.w;
                v = *(const float4*)&St_t[f][4 * ri]; At[0]=v.x; At[1]=v.y; At[2]=v.z; At[3]=v.w;
                v = *(const float4*)&St_t[f][4 * ci]; Bt[0]=v.x; Bt[1]=v.y; Bt[2]=v.z; Bt[3]=v.w;
                #pragma unroll
                for (int i = 0; i < 4; i++)
                    #pragma unroll
                    for (int j = 0; j < 4; j++) {
                        a_ss[i][j] += As[i] * Bs[j];
                        a_tt[i][j] += At[i] * Bt[j];
                        a_st[i][j] += As[i] * Bt[j];
                    }
            }
            float* p0 = &g_P[((0 * HL + t) * NCHUNK + nn) * 4096];
            float* p1 = &g_P[((1 * HL + t) * NCHUNK + nn) * 4096];
            float* p2 = &g_P[((2 * HL + t) * NCHUNK + nn) * 4096];
            #pragma unroll
            for (int i = 0; i < 4; i++) {
                int o = (4 * ri + i) * 64 + 4 * ci;
                *(float4*)&p0[o] = make_float4(a_ss[i][0], a_ss[i][1], a_ss[i][2], a_ss[i][3]);
                *(float4*)&p1[o] = make_float4(a_tt[i][0], a_tt[i][1], a_tt[i][2], a_tt[i][3]);
                *(float4*)&p2[o] = make_float4(a_st[i][0], a_st[i][1], a_st[i][2], a_st[i][3]);
            }
        }

        // ---- 32x32 node covariance (2x2 tile) ----
        {
            int ai = tid & 15, bi = tid >> 4;
            float cs[2][2] = {}, ct[2][2] = {};
            #pragma unroll 8
            for (int b = 0; b < BB; b++) {
                float2 va = *(const float2*)&Xs[b * DDIM + 2 * ai];
                float2 vb = *(const float2*)&Xs[b * DDIM + 2 * bi];
                float2 wa = *(const float2*)&Xt[b * DDIM + 2 * ai];
                float2 wb = *(const float2*)&Xt[b * DDIM + 2 * bi];
                cs[0][0] += va.x * vb.x; cs[0][1] += va.x * vb.y;
                cs[1][0] += va.y * vb.x; cs[1][1] += va.y * vb.y;
                ct[0][0] += wa.x * wb.x; ct[0][1] += wa.x * wb.y;
                ct[1][0] += wa.y * wb.x; ct[1][1] += wa.y * wb.y;
            }
            const float inv63 = 1.0f / 63.0f;
            int cbase = (t * NPTS + nn) * (DDIM * DDIM);
            #pragma unroll
            for (int i = 0; i < 2; i++)
                #pragma unroll
                for (int j = 0; j < 2; j++) {
                    int o = cbase + (2 * ai + i) * DDIM + (2 * bi + j);
                    g_C[0][o] = cs[i][j] * inv63;
                    g_C[1][o] = ct[i][j] * inv63;
                }
        }
    } else if (blk < 136) {
        // ---- L_sca for layer t ----
        int t = blk - 128;
        int base = t * (NPTS * NPTS) + tid;
        float ss = 0.f, sqs = 0.f, st = 0.f, sqt = 0.f;
        #pragma unroll 8
        for (int b = 0; b < BB; b++) {
            float a = Es[b * (HL * NPTS * NPTS) + base];
            ss += a; sqs += a * a;
            float ccc = Et[b * (HL * NPTS * NPTS) + base];
            st += ccc; sqt += ccc * ccc;
        }
        float var_s = (sqs - ss * ss * (1.0f / (float)BB)) * (1.0f / (float)(BB - 1));
        float var_t = (sqt - st * st * (1.0f / (float)BB)) * (1.0f / (float)(BB - 1));
        float d = var_s - var_t;
        red[tid] = d * d * 0.25f;
        __syncthreads();
        for (int s2 = 128; s2 > 0; s2 >>= 1) {
            if (tid < s2) red[tid] += red[tid + s2];
            __syncthreads();
        }
        if (tid == 0) g_sca[t] = red[0] * (1.0f / 256.0f);
    }
    // blocks 136..175: idle in phase 1

    grid_barrier();

    // ================= PHASE 2 (one task per block) =================
    if (blk < 128) {
        // sfa term for (t, n); warp w handles columns j = w, w+8
        int t = blk >> 4, n = blk & 15;
        int w = tid >> 5, lane = tid & 31;
        const float* Cs  = &g_C[0][(t * NPTS + n)     * (DDIM * DDIM)];
        const float* Ct1 = &g_C[1][(t * NPTS + w)     * (DDIM * DDIM)];
        const float* Ct2 = &g_C[1][(t * NPTS + w + 8) * (DDIM * DDIM)];
        float sqs = 0.f, d1 = 0.f, q1 = 0.f, d2 = 0.f, q2 = 0.f;
        #pragma unroll 8
        for (int k = lane; k < DDIM * DDIM; k += 32) {
            float a = Cs[k], b1 = Ct1[k], b2 = Ct2[k];
            sqs += a * a;
            d1 += a * b1; q1 += b1 * b1;
            d2 += a * b2; q2 += b2 * b2;
        }
        #pragma unroll
        for (int o = 16; o > 0; o >>= 1) {
            sqs += __shfl_xor_sync(0xFFFFFFFFu, sqs, o);
            d1  += __shfl_xor_sync(0xFFFFFFFFu, d1, o);
            q1  += __shfl_xor_sync(0xFFFFFFFFu, q1, o);
            d2  += __shfl_xor_sync(0xFFFFFFFFu, d2, o);
            q2  += __shfl_xor_sync(0xFFFFFFFFu, q2, o);
        }
        if (lane == 0) {
            sm_st[w] = d1;  sm_st[w + 8] = d2;
            sm_tt[w] = q1;  sm_tt[w + 8] = q2;
            if (w == 0) sm_ss = sqs;
        }
        __syncthreads();
        if (tid == 0) {
            float ss = sm_ss;
            float Dsum = 0.f, pos = 0.f;
            #pragma unroll
            for (int j = 0; j < 16; j++) {
                float Dj = (ss + sm_tt[j] - 2.0f * sm_st[j]) * (1.0f / 4096.0f);
                Dsum += Dj;
                if (j == n) pos = Dj;
            }
            float neg = Dsum - pos;
            float ep = expf(pos);
            g_sfa[t * NPTS + n] = logf(ep + neg + 1e-8f) - pos;
        }
    } else if (blk < 152) {
        // ||G_t||^2: reduce 16 chunk partials for gram g = type*8 + t
        int g = blk - 128;
        const float* Pbase = &g_P[g * NCHUNK * 4096];
        float sq = 0.f;
        for (int i = tid; i < 4096; i += 256) {
            float v = 0.f;
            #pragma unroll
            for (int c = 0; c < NCHUNK; c++) v += Pbase[c * 4096 + i];
            sq += v * v;
        }
        red[tid] = sq;
        __syncthreads();
        for (int s2 = 128; s2 > 0; s2 >>= 1) {
            if (tid < s2) red[tid] += red[tid + s2];
            __syncthreads();
        }
        if (tid == 0) g_Wnum[g] = red[0];
    } else {
        // full-Gram norm partial: sum 128 chunk partials per element
        int id = blk - 152;                   // 0..23
        int type = id >> 3, seg = id & 7;
        const float* Pbase = &g_P[type * HL * NCHUNK * 4096];
        float sq = 0.f;
        #pragma unroll
        for (int e = 0; e < 2; e++) {
            int i = seg * 512 + e * 256 + tid;
            float v = 0.f;
            #pragma unroll 8
            for (int tc = 0; tc < HL * NCHUNK; tc++)
                v += Pbase[tc * 4096 + i];
            sq += v * v;
        }
        red[tid] = sq;
        __syncthreads();
        for (int s2 = 128; s2 > 0; s2 >>= 1) {
            if (tid < s2) red[tid] += red[tid + s2];
            __syncthreads();
        }
        if (tid == 0) g_exo_part[type * 8 + seg] = red[0];
    }

    // ================= PHASE 3: last finisher combines =================
    __syncthreads();
    if (tid == 0) {
        __threadfence();
        unsigned int ticket = atomicAdd(&g_done, 1u);
        sm_last = ((ticket % NBLK) == (NBLK - 1)) ? 1u : 0u;
    }
    __syncthreads();
    if (sm_last && tid < 32) {
        __threadfence();
        int lane = tid;
        const float exo_scale = (float)(1.0 / (3969.0 * 4.0 * 16777216.0));
        const float w_scale   = (float)(1.0 / (3969.0 * 4.0 * 262144.0));
        float val = 0.f;
        if (lane < 8) {
            int t = lane;
            float W = (g_Wnum[t] + g_Wnum[HL + t] - 2.0f * g_Wnum[2 * HL + t]) * w_scale;
            float sfa = 0.f;
            #pragma unroll
            for (int n = 0; n < NPTS; n++) sfa += g_sfa[t * NPTS + n];
            sfa *= (1.0f / (float)NPTS);
            val = W * (0.1f * g_sca[t] + 0.1f * sfa) * (1.0f / (float)HL);
        } else {
            int id = lane - 8;                // 0..23
            int type = id >> 3, seg = id & 7;
            float coef = (type == 2) ? -2.0f : 1.0f;
            val = g_exo_part[type * 8 + seg] * coef * exo_scale;
        }
        #pragma unroll
        for (int o = 16; o > 0; o >>= 1)
            val += __shfl_xor_sync(0xFFFFFFFFu, val, o);
        if (lane == 0) out[0] = val;
    }
}

// ============================================================
extern "C" void kernel_launch(void* const* d_in, const int* in_sizes, int n_in,
                              void* d_out, int out_size) {
    const float* Zs = (const float*)d_in[0];
    const float* Es = (const float*)d_in[1];
    const float* Zt = (const float*)d_in[2];
    const float* Et = (const float*)d_in[3];
    float* out = (float*)d_out;

    fused_all<<<NBLK, 256>>>(Zs, Es, Zt, Et, out);
}

// round 6
// speedup vs baseline: 1.7213x; 1.3102x over previous
#include <cuda_runtime.h>

// Problem constants
#define BB      64      // batch
#define HL      8       // hat_L
#define NPTS    16      // N
#define DDIM    32      // d
#define FLAYER  512     // N*d
#define FTOT    4096    // hat_L*N*d
#define NCHUNK  16      // feature chunks per layer == nodes (CF == DDIM)
#define NBLK    224     // grid size (co-resident: 2 blocks/SM x 148 SMs = 296 >= 224)
// phase-1: 0..127 gram+cov (t,nn), 128..135 sca, 136..223 idle
// phase-2: 0..127 sfa, 128..175 Wnum halves, 176..223 exo quarter-segments

// -------- device scratch (no allocations allowed) --------
__device__ float g_P[3 * HL * NCHUNK * 4096];        // chunk Gram partials : 6 MB
__device__ float g_C[2][HL * NPTS * DDIM * DDIM];    // node covariances /63
__device__ float g_Wnum[48];                         // ||G_t||^2 halves: (type*8+t)*2+half
__device__ float g_exo_part[48];                     // type*16 + seg
__device__ float g_sca[HL];
__device__ float g_sfa[HL * NPTS];
__device__ unsigned int g_barcnt;                    // monotonic barrier ticket
__device__ unsigned int g_done;                      // completion ticket

// Replay-safe grid barrier: monotonic ticket counter, no reset needed.
__device__ __forceinline__ void grid_barrier() {
    __syncthreads();
    if (threadIdx.x == 0) {
        __threadfence();
        unsigned int ticket = atomicAdd(&g_barcnt, 1u);
        unsigned int target = (ticket / NBLK + 1u) * NBLK;
        while (true) {
            unsigned int v;
            asm volatile("ld.acquire.gpu.u32 %0, [%1];"
                         : "=r"(v) : "l"(&g_barcnt));
            if ((int)(v - target) >= 0) break;
            __nanosleep(32);
        }
    }
    __syncthreads();
}

__global__ void __launch_bounds__(256, 2) fused_all(
        const float* __restrict__ Zs, const float* __restrict__ Es,
        const float* __restrict__ Zt, const float* __restrict__ Et,
        float* __restrict__ out) {
    int blk = blockIdx.x, tid = threadIdx.x;

    __shared__ __align__(16) float St_s[DDIM][68];   // [f][b] transposed, padded
    __shared__ __align__(16) float St_t[DDIM][68];
    __shared__ __align__(16) float Xs[BB * DDIM];    // [b][f] row-major (cov path)
    __shared__ __align__(16) float Xt[BB * DDIM];
    __shared__ float sm_ps[DDIM * 8], sm_pt[DDIM * 8];   // mean partials
    __shared__ float sm_ms[DDIM], sm_mt[DDIM];           // means
    __shared__ float red[256];
    __shared__ float sm_st[16], sm_tt[16], sm_ss;
    __shared__ unsigned int sm_last;

    // ================= PHASE 1 =================
    if (blk < 128) {
        // combined gram-chunk + node-cov for (t, nn): slice 64 batch x 32 features
        int t = blk >> 4, nn = blk & 15;
        int fbase = t * FLAYER + nn * DDIM;
        int f0 = tid & 31, b0 = tid >> 5;
        float ps = 0.f, pt = 0.f;
        #pragma unroll
        for (int j = 0; j < 8; j++) {
            int b = b0 + 8 * j;
            float vs = Zs[b * FTOT + fbase + f0];
            float vt = Zt[b * FTOT + fbase + f0];
            St_s[f0][b] = vs; Xs[b * DDIM + f0] = vs; ps += vs;
            St_t[f0][b] = vt; Xt[b * DDIM + f0] = vt; pt += vt;
        }
        sm_ps[f0 * 8 + b0] = ps;
        sm_pt[f0 * 8 + b0] = pt;
        __syncthreads();
        if (tid < 64) {                       // reduce mean partials
            int f = tid & 31;
            float* P = (tid < 32) ? sm_ps : sm_pt;
            float m = 0.f;
            #pragma unroll
            for (int j = 0; j < 8; j++) m += P[f * 8 + j];
            m *= (1.0f / (float)BB);
            if (tid < 32) sm_ms[f] = m; else sm_mt[f] = m;
        }
        __syncthreads();
        {                                      // subtract means in both layouts
            float ms = sm_ms[f0], mt = sm_mt[f0];
            #pragma unroll
            for (int j = 0; j < 8; j++) {
                int b = b0 + 8 * j;
                St_s[f0][b] -= ms; Xs[b * DDIM + f0] -= ms;
                St_t[f0][b] -= mt; Xt[b * DDIM + f0] -= mt;
            }
        }
        __syncthreads();

        // ---- 64x64 batch-Gram partial (4x4 tile, coalesced stores) ----
        {
            int ri = tid >> 4, ci = tid & 15;
            float a_ss[4][4] = {}, a_tt[4][4] = {}, a_st[4][4] = {};
            #pragma unroll 4
            for (int f = 0; f < DDIM; f++) {
                float4 v;
                float As[4], Bs[4], At[4], Bt[4];
                v = *(const float4*)&St_s[f][4 * ri]; As[0]=v.x; As[1]=v.y; As[2]=v.z; As[3]=v.w;
                v = *(const float4*)&St_s[f][4 * ci]; Bs[0]=v.x; Bs[1]=v.y; Bs[2]=v.z; Bs[3]=v.w;
                v = *(const float4*)&St_t[f][4 * ri]; At[0]=v.x; At[1]=v.y; At[2]=v.z; At[3]=v.w;
                v = *(const float4*)&St_t[f][4 * ci]; Bt[0]=v.x; Bt[1]=v.y; Bt[2]=v.z; Bt[3]=v.w;
                #pragma unroll
                for (int i = 0; i < 4; i++)
                    #pragma unroll
                    for (int j = 0; j < 4; j++) {
                        a_ss[i][j] += As[i] * Bs[j];
                        a_tt[i][j] += At[i] * Bt[j];
                        a_st[i][j] += As[i] * Bt[j];
                    }
            }
            float* p0 = &g_P[((0 * HL + t) * NCHUNK + nn) * 4096];
            float* p1 = &g_P[((1 * HL + t) * NCHUNK + nn) * 4096];
            float* p2 = &g_P[((2 * HL + t) * NCHUNK + nn) * 4096];
            #pragma unroll
            for (int i = 0; i < 4; i++) {
                int o = (4 * ri + i) * 64 + 4 * ci;
                *(float4*)&p0[o] = make_float4(a_ss[i][0], a_ss[i][1], a_ss[i][2], a_ss[i][3]);
                *(float4*)&p1[o] = make_float4(a_tt[i][0], a_tt[i][1], a_tt[i][2], a_tt[i][3]);
                *(float4*)&p2[o] = make_float4(a_st[i][0], a_st[i][1], a_st[i][2], a_st[i][3]);
            }
        }

        // ---- 32x32 node covariance (2x2 tile) ----
        {
            int ai = tid & 15, bi = tid >> 4;
            float cs[2][2] = {}, ct[2][2] = {};
            #pragma unroll 8
            for (int b = 0; b < BB; b++) {
                float2 va = *(const float2*)&Xs[b * DDIM + 2 * ai];
                float2 vb = *(const float2*)&Xs[b * DDIM + 2 * bi];
                float2 wa = *(const float2*)&Xt[b * DDIM + 2 * ai];
                float2 wb = *(const float2*)&Xt[b * DDIM + 2 * bi];
                cs[0][0] += va.x * vb.x; cs[0][1] += va.x * vb.y;
                cs[1][0] += va.y * vb.x; cs[1][1] += va.y * vb.y;
                ct[0][0] += wa.x * wb.x; ct[0][1] += wa.x * wb.y;
                ct[1][0] += wa.y * wb.x; ct[1][1] += wa.y * wb.y;
            }
            const float inv63 = 1.0f / 63.0f;
            int cbase = (t * NPTS + nn) * (DDIM * DDIM);
            #pragma unroll
            for (int i = 0; i < 2; i++)
                #pragma unroll
                for (int j = 0; j < 2; j++) {
                    int o = cbase + (2 * ai + i) * DDIM + (2 * bi + j);
                    g_C[0][o] = cs[i][j] * inv63;
                    g_C[1][o] = ct[i][j] * inv63;
                }
        }
    } else if (blk < 136) {
        // ---- L_sca for layer t ----
        int t = blk - 128;
        int base = t * (NPTS * NPTS) + tid;
        float ss = 0.f, sqs = 0.f, st = 0.f, sqt = 0.f;
        #pragma unroll 8
        for (int b = 0; b < BB; b++) {
            float a = Es[b * (HL * NPTS * NPTS) + base];
            ss += a; sqs += a * a;
            float ccc = Et[b * (HL * NPTS * NPTS) + base];
            st += ccc; sqt += ccc * ccc;
        }
        float var_s = (sqs - ss * ss * (1.0f / (float)BB)) * (1.0f / (float)(BB - 1));
        float var_t = (sqt - st * st * (1.0f / (float)BB)) * (1.0f / (float)(BB - 1));
        float d = var_s - var_t;
        red[tid] = d * d * 0.25f;
        __syncthreads();
        for (int s2 = 128; s2 > 0; s2 >>= 1) {
            if (tid < s2) red[tid] += red[tid + s2];
            __syncthreads();
        }
        if (tid == 0) g_sca[t] = red[0] * (1.0f / 256.0f);
    }
    // blocks 136..223: idle in phase 1

    grid_barrier();

    // ================= PHASE 2 (one task per block) =================
    if (blk < 128) {
        // sfa term for (t, n); warp w handles columns j = w, w+8; float4 loads
        int t = blk >> 4, n = blk & 15;
        int w = tid >> 5, lane = tid & 31;
        const float* Cs  = &g_C[0][(t * NPTS + n)     * (DDIM * DDIM)];
        const float* Ct1 = &g_C[1][(t * NPTS + w)     * (DDIM * DDIM)];
        const float* Ct2 = &g_C[1][(t * NPTS + w + 8) * (DDIM * DDIM)];
        float sqs = 0.f, d1 = 0.f, q1 = 0.f, d2 = 0.f, q2 = 0.f;
        #pragma unroll
        for (int kk = 0; kk < 8; kk++) {
            int idx = kk * 128 + lane * 4;
            float4 a  = *(const float4*)&Cs[idx];
            float4 b1 = *(const float4*)&Ct1[idx];
            float4 b2 = *(const float4*)&Ct2[idx];
            sqs += a.x*a.x + a.y*a.y + a.z*a.z + a.w*a.w;
            d1  += a.x*b1.x + a.y*b1.y + a.z*b1.z + a.w*b1.w;
            q1  += b1.x*b1.x + b1.y*b1.y + b1.z*b1.z + b1.w*b1.w;
            d2  += a.x*b2.x + a.y*b2.y + a.z*b2.z + a.w*b2.w;
            q2  += b2.x*b2.x + b2.y*b2.y + b2.z*b2.z + b2.w*b2.w;
        }
        #pragma unroll
        for (int o = 16; o > 0; o >>= 1) {
            sqs += __shfl_xor_sync(0xFFFFFFFFu, sqs, o);
            d1  += __shfl_xor_sync(0xFFFFFFFFu, d1, o);
            q1  += __shfl_xor_sync(0xFFFFFFFFu, q1, o);
            d2  += __shfl_xor_sync(0xFFFFFFFFu, d2, o);
            q2  += __shfl_xor_sync(0xFFFFFFFFu, q2, o);
        }
        if (lane == 0) {
            sm_st[w] = d1;  sm_st[w + 8] = d2;
            sm_tt[w] = q1;  sm_tt[w + 8] = q2;
            if (w == 0) sm_ss = sqs;
        }
        __syncthreads();
        if (tid == 0) {
            float ss = sm_ss;
            float Dsum = 0.f, pos = 0.f;
            #pragma unroll
            for (int j = 0; j < 16; j++) {
                float Dj = (ss + sm_tt[j] - 2.0f * sm_st[j]) * (1.0f / 4096.0f);
                Dsum += Dj;
                if (j == n) pos = Dj;
            }
            float neg = Dsum - pos;
            float ep = expf(pos);
            g_sfa[t * NPTS + n] = logf(ep + neg + 1e-8f) - pos;
        }
    } else if (blk < 176) {
        // ||G_t||^2 half-range: id = (type*8+t)*2+half, 2048 elements, float4 loads
        int id = blk - 128;                   // 0..47
        int g = id >> 1, half = id & 1;
        const float* Pbase = &g_P[g * NCHUNK * 4096];
        float sq = 0.f;
        #pragma unroll
        for (int sslot = 0; sslot < 2; sslot++) {
            int i4 = (half * 512 + sslot * 256 + tid) * 4;
            float vx = 0.f, vy = 0.f, vz = 0.f, vw = 0.f;
            #pragma unroll 8
            for (int c = 0; c < NCHUNK; c++) {
                float4 p = *(const float4*)&Pbase[c * 4096 + i4];
                vx += p.x; vy += p.y; vz += p.z; vw += p.w;
            }
            sq += vx * vx + vy * vy + vz * vz + vw * vw;
        }
        red[tid] = sq;
        __syncthreads();
        for (int s2 = 128; s2 > 0; s2 >>= 1) {
            if (tid < s2) red[tid] += red[tid + s2];
            __syncthreads();
        }
        if (tid == 0) g_Wnum[id] = red[0];
    } else {
        // full-Gram norm quarter-segment: 256 elements, 128 chunk partials each
        int id = blk - 176;                   // 0..47
        int type = id >> 4, seg = id & 15;
        const float* Pbase = &g_P[type * HL * NCHUNK * 4096];
        int i = seg * 256 + tid;              // one element per thread
        float v = 0.f;
        #pragma unroll 16
        for (int tc = 0; tc < HL * NCHUNK; tc++)
            v += Pbase[tc * 4096 + i];
        red[tid] = v * v;
        __syncthreads();
        for (int s2 = 128; s2 > 0; s2 >>= 1) {
            if (tid < s2) red[tid] += red[tid + s2];
            __syncthreads();
        }
        if (tid == 0) g_exo_part[type * 16 + seg] = red[0];
    }

    // ================= PHASE 3: last finisher combines =================
    __syncthreads();
    if (tid == 0) {
        __threadfence();
        unsigned int ticket = atomicAdd(&g_done, 1u);
        sm_last = ((ticket % NBLK) == (NBLK - 1)) ? 1u : 0u;
    }
    __syncthreads();
    if (sm_last && tid < 32) {
        __threadfence();
        int lane = tid;
        const float exo_scale = (float)(1.0 / (3969.0 * 4.0 * 16777216.0));
        const float w_scale   = (float)(1.0 / (3969.0 * 4.0 * 262144.0));
        float val = 0.f;
        if (lane < 8) {
            int t = lane;
            float w0 = g_Wnum[(0 * HL + t) * 2] + g_Wnum[(0 * HL + t) * 2 + 1];
            float w1 = g_Wnum[(1 * HL + t) * 2] + g_Wnum[(1 * HL + t) * 2 + 1];
            float w2 = g_Wnum[(2 * HL + t) * 2] + g_Wnum[(2 * HL + t) * 2 + 1];
            float W = (w0 + w1 - 2.0f * w2) * w_scale;
            float sfa = 0.f;
            #pragma unroll
            for (int n = 0; n < NPTS; n++) sfa += g_sfa[t * NPTS + n];
            sfa *= (1.0f / (float)NPTS);
            val = W * (0.1f * g_sca[t] + 0.1f * sfa) * (1.0f / (float)HL);
        } else {
            int id = lane - 8;                // 0..23 -> (type, seg-pair)
            int type = id >> 3, pair = id & 7;
            float coef = (type == 2) ? -2.0f : 1.0f;
            val = (g_exo_part[type * 16 + 2 * pair] + g_exo_part[type * 16 + 2 * pair + 1])
                  * coef * exo_scale;
        }
        #pragma unroll
        for (int o = 16; o > 0; o >>= 1)
            val += __shfl_xor_sync(0xFFFFFFFFu, val, o);
        if (lane == 0) out[0] = val;
    }
}

// ============================================================
extern "C" void kernel_launch(void* const* d_in, const int* in_sizes, int n_in,
                              void* d_out, int out_size) {
    const float* Zs = (const float*)d_in[0];
    const float* Es = (const float*)d_in[1];
    const float* Zt = (const float*)d_in[2];
    const float* Et = (const float*)d_in[3];
    float* out = (float*)d_out;

    fused_all<<<NBLK, 256>>>(Zs, Es, Zt, Et, out);
}

// round 7
// speedup vs baseline: 1.8684x; 1.0855x over previous
#include <cuda_runtime.h>

// Problem constants
#define BB      64      // batch
#define HL      8       // hat_L
#define NPTS    16      // N
#define DDIM    32      // d
#define FLAYER  512     // N*d
#define FTOT    4096    // hat_L*N*d
#define NCHUNK  16      // feature chunks per layer == nodes (CF == DDIM)
#define NBLK    176     // grid size (all co-resident)
// phase-1: 0..127 gram+cov (t,nn), 128..135 sca, 136..175 idle
// phase-2: 0..127 sfa, 128..175 fused Wnum+exo (type,seg)

// -------- device scratch (no allocations allowed) --------
__device__ float g_P[3 * HL * NCHUNK * 4096];        // chunk Gram partials : 6 MB
__device__ float g_C[2][HL * NPTS * DDIM * DDIM];    // node covariances /63
__device__ float g_Wpart[48 * 8];                    // per-(type,seg) per-layer norm partials
__device__ float g_exo_part[48];                     // per-(type,seg) exo norm partials
__device__ float g_sca[HL];
__device__ float g_sfa[HL * NPTS];
__device__ unsigned int g_barcnt;                    // monotonic barrier ticket
__device__ unsigned int g_done;                      // completion ticket

// 16x16 tile-grid triangle enumerations
__device__ __forceinline__ void upper_from_idx(int idx, int& r, int& c) {
    int rr = 0, start = 0;
    while (start + (16 - rr) <= idx) { start += 16 - rr; rr++; }
    r = rr; c = rr + (idx - start);
}
__device__ __forceinline__ void lower_from_idx(int idx, int& r, int& c) {
    int rr = 1, start = 0;
    while (start + rr <= idx) { start += rr; rr++; }
    r = rr; c = idx - start;
}

// Replay-safe grid barrier: monotonic ticket counter, no reset needed.
__device__ __forceinline__ void grid_barrier() {
    __syncthreads();
    if (threadIdx.x == 0) {
        __threadfence();
        unsigned int ticket = atomicAdd(&g_barcnt, 1u);
        unsigned int target = (ticket / NBLK + 1u) * NBLK;
        while (true) {
            unsigned int v;
            asm volatile("ld.acquire.gpu.u32 %0, [%1];"
                         : "=r"(v) : "l"(&g_barcnt));
            if ((int)(v - target) >= 0) break;
            __nanosleep(32);
        }
    }
    __syncthreads();
}

__global__ void __launch_bounds__(256, 2) fused_all(
        const float* __restrict__ Zs, const float* __restrict__ Es,
        const float* __restrict__ Zt, const float* __restrict__ Et,
        float* __restrict__ out) {
    int blk = blockIdx.x, tid = threadIdx.x;

    __shared__ __align__(16) float St_s[DDIM][68];   // [f][b] transposed, padded
    __shared__ __align__(16) float St_t[DDIM][68];
    __shared__ float sm_ps[DDIM * 8], sm_pt[DDIM * 8];   // mean partials
    __shared__ float sm_ms[DDIM], sm_mt[DDIM];           // means
    __shared__ float red[256];
    __shared__ float sm_st[16], sm_tt[16], sm_ss;
    __shared__ float smr[8][9];
    __shared__ unsigned int sm_last;

    // ================= PHASE 1 =================
    if (blk < 128) {
        // slice (t, nn): 64 batch x 32 features, load + center into St (transposed)
        int t = blk >> 4, nn = blk & 15;
        int fbase = t * FLAYER + nn * DDIM;
        int f0 = tid & 31, b0 = tid >> 5;
        float ps = 0.f, pt = 0.f;
        #pragma unroll
        for (int j = 0; j < 8; j++) {
            int b = b0 + 8 * j;
            float vs = Zs[b * FTOT + fbase + f0];
            float vt = Zt[b * FTOT + fbase + f0];
            St_s[f0][b] = vs; ps += vs;
            St_t[f0][b] = vt; pt += vt;
        }
        sm_ps[f0 * 8 + b0] = ps;
        sm_pt[f0 * 8 + b0] = pt;
        __syncthreads();
        if (tid < 64) {                       // reduce mean partials
            int f = tid & 31;
            float* P = (tid < 32) ? sm_ps : sm_pt;
            float m = 0.f;
            #pragma unroll
            for (int j = 0; j < 8; j++) m += P[f * 8 + j];
            m *= (1.0f / (float)BB);
            if (tid < 32) sm_ms[f] = m; else sm_mt[f] = m;
        }
        __syncthreads();
        {                                      // subtract means
            float ms = sm_ms[f0], mt = sm_mt[f0];
            #pragma unroll
            for (int j = 0; j < 8; j++) {
                int b = b0 + 8 * j;
                St_s[f0][b] -= ms;
                St_t[f0][b] -= mt;
            }
        }
        __syncthreads();

        float* p0 = &g_P[((0 * HL + t) * NCHUNK + nn) * 4096];
        float* p1 = &g_P[((1 * HL + t) * NCHUNK + nn) * 4096];
        float* p2 = &g_P[((2 * HL + t) * NCHUNK + nn) * 4096];
        int w = tid >> 5;

        if (w < 5) {
            // ---- 3-type 4x4 tile: 136 upper tiles + 24 padding (lower, st-store-only) ----
            int r, c;
            bool is_upper = (tid < 136);
            if (is_upper) upper_from_idx(tid, r, c);
            else          lower_from_idx(tid - 136, r, c);

            float a_ss[4][4] = {}, a_tt[4][4] = {}, a_st[4][4] = {};
            #pragma unroll 4
            for (int f = 0; f < DDIM; f++) {
                float4 v;
                float As[4], Bs[4], At[4], Bt[4];
                v = *(const float4*)&St_s[f][4 * r]; As[0]=v.x; As[1]=v.y; As[2]=v.z; As[3]=v.w;
                v = *(const float4*)&St_s[f][4 * c]; Bs[0]=v.x; Bs[1]=v.y; Bs[2]=v.z; Bs[3]=v.w;
                v = *(const float4*)&St_t[f][4 * r]; At[0]=v.x; At[1]=v.y; At[2]=v.z; At[3]=v.w;
                v = *(const float4*)&St_t[f][4 * c]; Bt[0]=v.x; Bt[1]=v.y; Bt[2]=v.z; Bt[3]=v.w;
                #pragma unroll
                for (int i = 0; i < 4; i++)
                    #pragma unroll
                    for (int j = 0; j < 4; j++) {
                        a_ss[i][j] += As[i] * Bs[j];
                        a_tt[i][j] += At[i] * Bt[j];
                        a_st[i][j] += As[i] * Bt[j];
                    }
            }
            // st stored always (st not symmetric; padding slots own their lower tile)
            #pragma unroll
            for (int i = 0; i < 4; i++)
                *(float4*)&p2[(4 * r + i) * 64 + 4 * c] =
                    make_float4(a_st[i][0], a_st[i][1], a_st[i][2], a_st[i][3]);
            if (is_upper) {
                #pragma unroll
                for (int i = 0; i < 4; i++) {
                    int o = (4 * r + i) * 64 + 4 * c;
                    *(float4*)&p0[o] = make_float4(a_ss[i][0], a_ss[i][1], a_ss[i][2], a_ss[i][3]);
                    *(float4*)&p1[o] = make_float4(a_tt[i][0], a_tt[i][1], a_tt[i][2], a_tt[i][3]);
                }
                if (r < c) {                   // mirror (bitwise-equal values)
                    #pragma unroll
                    for (int j = 0; j < 4; j++) {
                        int o = (4 * c + j) * 64 + 4 * r;
                        *(float4*)&p0[o] = make_float4(a_ss[0][j], a_ss[1][j], a_ss[2][j], a_ss[3][j]);
                        *(float4*)&p1[o] = make_float4(a_tt[0][j], a_tt[1][j], a_tt[2][j], a_tt[3][j]);
                    }
                }
            }
        } else {
            // ---- st-only 4x4 tile (lower tiles 24..119) + node covariance ----
            int lid160 = tid - 160;           // 0..95
            int r, c;
            lower_from_idx(24 + lid160, r, c);
            float a_st[4][4] = {};
            #pragma unroll 4
            for (int f = 0; f < DDIM; f++) {
                float4 v;
                float As[4], Bt[4];
                v = *(const float4*)&St_s[f][4 * r]; As[0]=v.x; As[1]=v.y; As[2]=v.z; As[3]=v.w;
                v = *(const float4*)&St_t[f][4 * c]; Bt[0]=v.x; Bt[1]=v.y; Bt[2]=v.z; Bt[3]=v.w;
                #pragma unroll
                for (int i = 0; i < 4; i++)
                    #pragma unroll
                    for (int j = 0; j < 4; j++)
                        a_st[i][j] += As[i] * Bt[j];
            }
            #pragma unroll
            for (int i = 0; i < 4; i++)
                *(float4*)&p2[(4 * r + i) * 64 + 4 * c] =
                    make_float4(a_st[i][0], a_st[i][1], a_st[i][2], a_st[i][3]);

            // node covariance: C[i][j] = dot(St row i, St row j) / 63, symmetric.
            // 2x2 tiles over 16x16 grid, upper triangle (136 tiles) + mirrors.
            const float inv63 = 1.0f / 63.0f;
            int cbase = (t * NPTS + nn) * (DDIM * DDIM);
            #pragma unroll
            for (int u = 0; u < 2; u++) {
                int cidx = lid160 + 96 * u;
                if (cidx < 136) {
                    int r2, c2;
                    upper_from_idx(cidx, r2, c2);
                    float cs[2][2] = {}, ct[2][2] = {};
                    #pragma unroll 4
                    for (int k = 0; k < 16; k++) {
                        float4 su0 = *(const float4*)&St_s[2 * r2][4 * k];
                        float4 su1 = *(const float4*)&St_s[2 * r2 + 1][4 * k];
                        float4 sv0 = *(const float4*)&St_s[2 * c2][4 * k];
                        float4 sv1 = *(const float4*)&St_s[2 * c2 + 1][4 * k];
                        cs[0][0] += su0.x*sv0.x + su0.y*sv0.y + su0.z*sv0.z + su0.w*sv0.w;
                        cs[0][1] += su0.x*sv1.x + su0.y*sv1.y + su0.z*sv1.z + su0.w*sv1.w;
                        cs[1][0] += su1.x*sv0.x + su1.y*sv0.y + su1.z*sv0.z + su1.w*sv0.w;
                        cs[1][1] += su1.x*sv1.x + su1.y*sv1.y + su1.z*sv1.z + su1.w*sv1.w;
                        float4 tu0 = *(const float4*)&St_t[2 * r2][4 * k];
                        float4 tu1 = *(const float4*)&St_t[2 * r2 + 1][4 * k];
                        float4 tv0 = *(const float4*)&St_t[2 * c2][4 * k];
                        float4 tv1 = *(const float4*)&St_t[2 * c2 + 1][4 * k];
                        ct[0][0] += tu0.x*tv0.x + tu0.y*tv0.y + tu0.z*tv0.z + tu0.w*tv0.w;
                        ct[0][1] += tu0.x*tv1.x + tu0.y*tv1.y + tu0.z*tv1.z + tu0.w*tv1.w;
                        ct[1][0] += tu1.x*tv0.x + tu1.y*tv0.y + tu1.z*tv0.z + tu1.w*tv0.w;
                        ct[1][1] += tu1.x*tv1.x + tu1.y*tv1.y + tu1.z*tv1.z + tu1.w*tv1.w;
                    }
                    #pragma unroll
                    for (int i = 0; i < 2; i++)
                        #pragma unroll
                        for (int j = 0; j < 2; j++) {
                            int o = cbase + (2 * r2 + i) * DDIM + (2 * c2 + j);
                            g_C[0][o] = cs[i][j] * inv63;
                            g_C[1][o] = ct[i][j] * inv63;
                        }
                    if (r2 < c2) {
                        #pragma unroll
                        for (int i = 0; i < 2; i++)
                            #pragma unroll
                            for (int j = 0; j < 2; j++) {
                                int o = cbase + (2 * c2 + j) * DDIM + (2 * r2 + i);
                                g_C[0][o] = cs[i][j] * inv63;
                                g_C[1][o] = ct[i][j] * inv63;
                            }
                    }
                }
            }
        }
    } else if (blk < 136) {
        // ---- L_sca for layer t ----
        int t = blk - 128;
        int base = t * (NPTS * NPTS) + tid;
        float ss = 0.f, sqs = 0.f, st = 0.f, sqt = 0.f;
        #pragma unroll 8
        for (int b = 0; b < BB; b++) {
            float a = Es[b * (HL * NPTS * NPTS) + base];
            ss += a; sqs += a * a;
            float ccc = Et[b * (HL * NPTS * NPTS) + base];
            st += ccc; sqt += ccc * ccc;
        }
        float var_s = (sqs - ss * ss * (1.0f / (float)BB)) * (1.0f / (float)(BB - 1));
        float var_t = (sqt - st * st * (1.0f / (float)BB)) * (1.0f / (float)(BB - 1));
        float d = var_s - var_t;
        red[tid] = d * d * 0.25f;
        __syncthreads();
        for (int s2 = 128; s2 > 0; s2 >>= 1) {
            if (tid < s2) red[tid] += red[tid + s2];
            __syncthreads();
        }
        if (tid == 0) g_sca[t] = red[0] * (1.0f / 256.0f);
    }
    // blocks 136..175: idle in phase 1

    grid_barrier();

    // ================= PHASE 2 (one task per block) =================
    if (blk < 128) {
        // sfa term for (t, n); warp w handles columns j = w, w+8; float4 loads
        int t = blk >> 4, n = blk & 15;
        int w = tid >> 5, lane = tid & 31;
        const float* Cs  = &g_C[0][(t * NPTS + n)     * (DDIM * DDIM)];
        const float* Ct1 = &g_C[1][(t * NPTS + w)     * (DDIM * DDIM)];
        const float* Ct2 = &g_C[1][(t * NPTS + w + 8) * (DDIM * DDIM)];
        float sqs = 0.f, d1 = 0.f, q1 = 0.f, d2 = 0.f, q2 = 0.f;
        #pragma unroll
        for (int kk = 0; kk < 8; kk++) {
            int idx = kk * 128 + lane * 4;
            float4 a  = *(const float4*)&Cs[idx];
            float4 b1 = *(const float4*)&Ct1[idx];
            float4 b2 = *(const float4*)&Ct2[idx];
            sqs += a.x*a.x + a.y*a.y + a.z*a.z + a.w*a.w;
            d1  += a.x*b1.x + a.y*b1.y + a.z*b1.z + a.w*b1.w;
            q1  += b1.x*b1.x + b1.y*b1.y + b1.z*b1.z + b1.w*b1.w;
            d2  += a.x*b2.x + a.y*b2.y + a.z*b2.z + a.w*b2.w;
            q2  += b2.x*b2.x + b2.y*b2.y + b2.z*b2.z + b2.w*b2.w;
        }
        #pragma unroll
        for (int o = 16; o > 0; o >>= 1) {
            sqs += __shfl_xor_sync(0xFFFFFFFFu, sqs, o);
            d1  += __shfl_xor_sync(0xFFFFFFFFu, d1, o);
            q1  += __shfl_xor_sync(0xFFFFFFFFu, q1, o);
            d2  += __shfl_xor_sync(0xFFFFFFFFu, d2, o);
            q2  += __shfl_xor_sync(0xFFFFFFFFu, q2, o);
        }
        if (lane == 0) {
            sm_st[w] = d1;  sm_st[w + 8] = d2;
            sm_tt[w] = q1;  sm_tt[w + 8] = q2;
            if (w == 0) sm_ss = sqs;
        }
        __syncthreads();
        if (tid == 0) {
            float ss = sm_ss;
            float Dsum = 0.f, pos = 0.f;
            #pragma unroll
            for (int j = 0; j < 16; j++) {
                float Dj = (ss + sm_tt[j] - 2.0f * sm_st[j]) * (1.0f / 4096.0f);
                Dsum += Dj;
                if (j == n) pos = Dj;
            }
            float neg = Dsum - pos;
            float ep = expf(pos);
            g_sfa[t * NPTS + n] = logf(ep + neg + 1e-8f) - pos;
        }
    } else {
        // fused Wnum + exo partial: (type, seg), element i = seg*256 + tid
        int id = blk - 128;                   // 0..47
        int type = id >> 4, seg = id & 15;
        const float* Pbase = &g_P[type * HL * NCHUNK * 4096];
        int i = seg * 256 + tid;
        float e = 0.f;
        float wv[9];
        #pragma unroll
        for (int t = 0; t < HL; t++) {
            float v = 0.f;
            #pragma unroll
            for (int c = 0; c < NCHUNK; c++)
                v += Pbase[(t * NCHUNK + c) * 4096 + i];
            wv[t] = v * v;
            e += v;
        }
        wv[8] = e * e;
        int w = tid >> 5, lane = tid & 31;
        #pragma unroll
        for (int k = 0; k < 9; k++) {
            float s = wv[k];
            #pragma unroll
            for (int o = 16; o > 0; o >>= 1)
                s += __shfl_xor_sync(0xFFFFFFFFu, s, o);
            if (lane == 0) smr[w][k] = s;
        }
        __syncthreads();
        if (tid < 9) {
            float s = 0.f;
            #pragma unroll
            for (int ww = 0; ww < 8; ww++) s += smr[ww][tid];
            if (tid < 8) g_Wpart[id * 8 + tid] = s;
            else         g_exo_part[id] = s;
        }
    }

    // ================= PHASE 3: last finisher combines =================
    __syncthreads();
    if (tid == 0) {
        __threadfence();
        unsigned int ticket = atomicAdd(&g_done, 1u);
        sm_last = ((ticket % NBLK) == (NBLK - 1)) ? 1u : 0u;
    }
    __syncthreads();
    if (sm_last && tid < 32) {
        __threadfence();
        int lane = tid;
        const float exo_scale = (float)(1.0 / (3969.0 * 4.0 * 16777216.0));
        const float w_scale   = (float)(1.0 / (3969.0 * 4.0 * 262144.0));
        float val = 0.f;
        if (lane < 8) {
            int t = lane;
            float w0 = 0.f, w1 = 0.f, w2 = 0.f;
            #pragma unroll
            for (int seg = 0; seg < 16; seg++) {
                w0 += g_Wpart[(0 * 16 + seg) * 8 + t];
                w1 += g_Wpart[(1 * 16 + seg) * 8 + t];
                w2 += g_Wpart[(2 * 16 + seg) * 8 + t];
            }
            float W = (w0 + w1 - 2.0f * w2) * w_scale;
            float sfa = 0.f;
            #pragma unroll
            for (int n = 0; n < NPTS; n++) sfa += g_sfa[t * NPTS + n];
            sfa *= (1.0f / (float)NPTS);
            val = W * (0.1f * g_sca[t] + 0.1f * sfa) * (1.0f / (float)HL);
        } else {
            int idA = (lane - 8) * 2, idB = idA + 1;    // 0..47
            float cA = ((idA >> 4) == 2) ? -2.0f : 1.0f;
            float cB = ((idB >> 4) == 2) ? -2.0f : 1.0f;
            val = (g_exo_part[idA] * cA + g_exo_part[idB] * cB) * exo_scale;
        }
        #pragma unroll
        for (int o = 16; o > 0; o >>= 1)
            val += __shfl_xor_sync(0xFFFFFFFFu, val, o);
        if (lane == 0) out[0] = val;
    }
}

// ============================================================
extern "C" void kernel_launch(void* const* d_in, const int* in_sizes, int n_in,
                              void* d_out, int out_size) {
    const float* Zs = (const float*)d_in[0];
    const float* Es = (const float*)d_in[1];
    const float* Zt = (const float*)d_in[2];
    const float* Et = (const float*)d_in[3];
    float* out = (float*)d_out;

    fused_all<<<NBLK, 256>>>(Zs, Es, Zt, Et, out);
}